// round 12
// baseline (speedup 1.0000x reference)
#include <cuda_runtime.h>
#include <stdint.h>

#define NMAX 100000
#define EMAX 1600000

// ---------------- scratch (device globals; referenced DIRECTLY by kernels) --
__device__ int    g_is64;               // 1 if edge_index is int64, else int32
__device__ int    g_deg[NMAX];          // in-degree (excl. self-loop)
__device__ float  g_dis[NMAX];          // rsqrt(deg+1)
__device__ int    g_src[EMAX];
__device__ int    g_dst[EMAX];
__device__ int    g_rowptr[NMAX];       // exclusive prefix of deg
__device__ int    g_cursor[NMAX];
__device__ int    g_blksum[1024];
__device__ int2   g_csr[EMAX];          // {src, bitcast(norm)} grouped by dst
__device__ float4 g_h1[(size_t)NMAX * 32];   // x @ W1            [N,128]
__device__ float4 g_a1[(size_t)NMAX * 32];   // aggregated layer1 [N,128]
__device__ float4 g_h2[(size_t)NMAX * 16];   // relu(a1) @ W2     [N,64]

// ---------------- dtype detection ------------------------------------------
// int64 layout: each value's high 32-bit word is 0 (values in [0, N)).
// int32 layout: odd words are edge values, ~never all zero across 32 samples.
__global__ void k_detect(const int* __restrict__ w) {
    int t = threadIdx.x;                 // 0..31
    int v = w[2 * t + 1];
    unsigned nz = __ballot_sync(0xffffffffu, v != 0);
    if (t == 0) g_is64 = (nz == 0u) ? 1 : 0;
}

// ---------------- preprocessing --------------------------------------------
__global__ void k_zero(int n) {
    int i = blockIdx.x * blockDim.x + threadIdx.x;
    if (i < n) g_deg[i] = 0;
}

__global__ void k_count(const int* __restrict__ w, int E, int n) {
    int e = blockIdx.x * blockDim.x + threadIdx.x;
    if (e >= E) return;
    int s, d;
    if (g_is64) { s = w[2 * e];  d = w[2 * E + 2 * e]; }
    else        { s = w[e];      d = w[E + e]; }
    s = min(max(s, 0), n - 1);
    d = min(max(d, 0), n - 1);
    g_src[e] = s;
    g_dst[e] = d;
    atomicAdd(&g_deg[d], 1);
}

__global__ void k_dis(int n) {
    int i = blockIdx.x * blockDim.x + threadIdx.x;
    if (i < n) g_dis[i] = rsqrtf((float)g_deg[i] + 1.0f);  // +1 self-loop
}

// exclusive scan of g_deg -> g_rowptr (3 phases)
__global__ void k_scan1(int n) {
    __shared__ int s[256];
    int t = threadIdx.x;
    int i = blockIdx.x * 256 + t;
    int v = (i < n) ? g_deg[i] : 0;
    s[t] = v;
    __syncthreads();
#pragma unroll
    for (int off = 1; off < 256; off <<= 1) {
        int u = (t >= off) ? s[t - off] : 0;
        __syncthreads();
        s[t] += u;
        __syncthreads();
    }
    if (i < n) g_rowptr[i] = s[t] - v;
    if (t == 255) g_blksum[blockIdx.x] = s[255];
}

__global__ void k_scan2(int nb) {
    __shared__ int s[512];
    int t = threadIdx.x;
    int v = (t < nb) ? g_blksum[t] : 0;
    s[t] = v;
    __syncthreads();
#pragma unroll
    for (int off = 1; off < 512; off <<= 1) {
        int u = (t >= off) ? s[t - off] : 0;
        __syncthreads();
        s[t] += u;
        __syncthreads();
    }
    if (t < nb) g_blksum[t] = s[t] - v;  // exclusive over blocks
}

__global__ void k_scan3(int n) {
    int i = blockIdx.x * blockDim.x + threadIdx.x;
    if (i < n) {
        int r = g_rowptr[i] + g_blksum[i >> 8];
        g_rowptr[i] = r;
        g_cursor[i] = r;
    }
}

__global__ void k_fill(int E) {
    int e = blockIdx.x * blockDim.x + threadIdx.x;
    if (e < E) {
        int s = g_src[e];
        int d = g_dst[e];
        int pos = atomicAdd(&g_cursor[d], 1);
        g_csr[pos] = make_int2(s, __float_as_int(g_dis[s] * g_dis[d]));
    }
}

// ---------------- register-tiled FP32 GEMM ----------------------------------
// COUT=128: X = Xext (harness x), H = g_h1.   COUT=64: X = g_a1 (+relu), H = g_h2.
template <int COUT, bool RELU_IN>
__global__ void k_gemm(const float* __restrict__ Xext, const float* __restrict__ W,
                       int nrows) {
    const float* X;
    float*       H;
    if constexpr (COUT == 128) { X = Xext;                 H = (float*)g_h1; }
    else                       { X = (const float*)g_a1;   H = (float*)g_h2; }

    constexpr int CG   = COUT / 8;
    constexpr int RG   = 256 / CG;
    constexpr int ROWS = RG * 4;
    constexpr int KC   = 32;

    __shared__ float xs[ROWS][KC + 4];
    __shared__ float ws[KC][COUT];

    const int tid  = threadIdx.x;
    const int txc  = tid % CG;
    const int tyr  = tid / CG;
    const int row0 = blockIdx.x * ROWS;

    float acc[4][8];
#pragma unroll
    for (int i = 0; i < 4; i++)
#pragma unroll
        for (int j = 0; j < 8; j++) acc[i][j] = 0.0f;

    for (int kc = 0; kc < 128; kc += KC) {
#pragma unroll
        for (int it = 0; it < (KC * COUT) / (256 * 4); it++) {
            int i4 = tid + it * 256;
            ((float4*)&ws[0][0])[i4] =
                *(const float4*)&W[(size_t)kc * COUT + (size_t)i4 * 4];
        }
#pragma unroll
        for (int it = 0; it < (ROWS * KC) / (256 * 4); it++) {
            int i4 = tid + it * 256;
            int r  = i4 / (KC / 4);
            int k4 = i4 % (KC / 4);
            int rg = row0 + r;
            float4 v = make_float4(0.f, 0.f, 0.f, 0.f);
            if (rg < nrows)
                v = *(const float4*)&X[(size_t)rg * 128 + kc + k4 * 4];
            if (RELU_IN) {
                v.x = fmaxf(v.x, 0.f); v.y = fmaxf(v.y, 0.f);
                v.z = fmaxf(v.z, 0.f); v.w = fmaxf(v.w, 0.f);
            }
            *(float4*)&xs[r][k4 * 4] = v;
        }
        __syncthreads();

#pragma unroll
        for (int kk = 0; kk < KC; kk++) {
            float a0 = xs[tyr * 4 + 0][kk];
            float a1 = xs[tyr * 4 + 1][kk];
            float a2 = xs[tyr * 4 + 2][kk];
            float a3 = xs[tyr * 4 + 3][kk];
            float4 b0 = *(const float4*)&ws[kk][txc * 8];
            float4 b1 = *(const float4*)&ws[kk][txc * 8 + 4];
            float bb[8] = {b0.x, b0.y, b0.z, b0.w, b1.x, b1.y, b1.z, b1.w};
#pragma unroll
            for (int j = 0; j < 8; j++) {
                acc[0][j] = fmaf(a0, bb[j], acc[0][j]);
                acc[1][j] = fmaf(a1, bb[j], acc[1][j]);
                acc[2][j] = fmaf(a2, bb[j], acc[2][j]);
                acc[3][j] = fmaf(a3, bb[j], acc[3][j]);
            }
        }
        __syncthreads();
    }

#pragma unroll
    for (int i = 0; i < 4; i++) {
        int r = row0 + tyr * 4 + i;
        if (r < nrows) {
            float4 s0 = make_float4(acc[i][0], acc[i][1], acc[i][2], acc[i][3]);
            float4 s1 = make_float4(acc[i][4], acc[i][5], acc[i][6], acc[i][7]);
            float4* hp = (float4*)&H[(size_t)r * COUT + txc * 8];
            hp[0] = s0;
            hp[1] = s1;
        }
    }
}

// ---------------- CSR gather-aggregate: out[i] = b + dis[i]^2*h[i] + sum ----
// C4=32: h = g_h1, out = g_a1.   C4=16: h = g_h2, out = outext (d_out).
template <int C4>
__global__ void k_gather(const float* __restrict__ bias, float4* __restrict__ outext,
                         int n) {
    const float4* h;
    float4*       out;
    if constexpr (C4 == 32) { h = g_h1; out = g_a1; }
    else                    { h = g_h2; out = outext; }

    int t = blockIdx.x * blockDim.x + threadIdx.x;
    int i = t / C4;
    int q = t % C4;
    if (i >= n) return;

    int   beg = g_rowptr[i];
    int   cnt = g_deg[i];
    float d   = g_dis[i];
    float d2  = d * d;

    float4 hv = h[(size_t)i * C4 + q];
    float4 bv = ((const float4*)bias)[q];
    float4 acc;
    acc.x = fmaf(hv.x, d2, bv.x);
    acc.y = fmaf(hv.y, d2, bv.y);
    acc.z = fmaf(hv.z, d2, bv.z);
    acc.w = fmaf(hv.w, d2, bv.w);

    int2 nxt = (cnt > 0) ? g_csr[beg] : make_int2(0, 0);
    for (int e = 0; e < cnt; e++) {
        int2 cur = nxt;
        if (e + 1 < cnt) nxt = g_csr[beg + e + 1];   // prefetch next edge
        float  w = __int_as_float(cur.y);
        float4 v = h[(size_t)cur.x * C4 + q];
        acc.x = fmaf(v.x, w, acc.x);
        acc.y = fmaf(v.y, w, acc.y);
        acc.z = fmaf(v.z, w, acc.z);
        acc.w = fmaf(v.w, w, acc.w);
    }
    out[(size_t)i * C4 + q] = acc;
}

// ---------------- launch -----------------------------------------------------
extern "C" void kernel_launch(void* const* d_in, const int* in_sizes, int n_in,
                              void* d_out, int out_size) {
    const float* x  = (const float*)d_in[0];
    const int*   ew = (const int*)d_in[1];    // int32 view of edge buffer
    const float* W1 = (const float*)d_in[2];
    const float* b1 = (const float*)d_in[3];
    const float* W2 = (const float*)d_in[4];
    const float* b2 = (const float*)d_in[5];

    const int N  = in_sizes[0] / 128;
    const int E  = in_sizes[1] / 2;
    const int nb = (N + 255) / 256;
    const int T  = 256;

    // ---- edge dtype detect + normalization + dst-grouped CSR ----
    k_detect<<<1, 32>>>(ew);
    k_zero  <<<nb, T>>>(N);
    k_count <<<(E + T - 1) / T, T>>>(ew, E, N);
    k_dis   <<<nb, T>>>(N);
    k_scan1 <<<nb, T>>>(N);
    k_scan2 <<<1, 512>>>(nb);
    k_scan3 <<<nb, T>>>(N);
    k_fill  <<<(E + T - 1) / T, T>>>(E);

    // ---- layer 1: h1 = x @ W1 ; a1 = b1 + dis^2*h1 + gathered sum ----
    k_gemm<128, false><<<(N + 63) / 64, T>>>(x, W1, N);
    k_gather<32><<<(N * 32 + T - 1) / T, T>>>(b1, nullptr, N);

    // ---- layer 2: h2 = relu(a1) @ W2 ; out = b2 + dis^2*h2 + sum ----
    k_gemm<64, true><<<(N + 127) / 128, T>>>(nullptr, W2, N);
    k_gather<16><<<(N * 16 + T - 1) / T, T>>>(b2, (float4*)d_out, N);
}

// round 14
// speedup vs baseline: 1.4816x; 1.4816x over previous
#include <cuda_runtime.h>
#include <stdint.h>

#define NMAX 100000
#define EMAX 1600000

// ---------------- scratch (device globals; referenced DIRECTLY by kernels) --
__device__ int    g_is64;               // 1 if edge_index is int64, else int32
__device__ int    g_deg[NMAX];          // in-degree (excl. self-loop)
__device__ float  g_dis[NMAX];          // rsqrt(deg+1)
__device__ int    g_src[EMAX];
__device__ int    g_dst[EMAX];
__device__ int    g_rowptr[NMAX];       // exclusive prefix of deg
__device__ int    g_cursor[NMAX];
__device__ int    g_blksum[1024];
__device__ int2   g_csr[EMAX];          // {src, bitcast(norm)} grouped by dst
__device__ float4 g_h1[(size_t)NMAX * 32];   // x @ W1            [N,128]
__device__ float4 g_a1[(size_t)NMAX * 32];   // aggregated layer1 [N,128]
__device__ float4 g_h2[(size_t)NMAX * 16];   // relu(a1) @ W2     [N,64]

// ---------------- dtype detection ------------------------------------------
__global__ void k_detect(const int* __restrict__ w) {
    int t = threadIdx.x;                 // 0..31
    int v = w[2 * t + 1];
    unsigned nz = __ballot_sync(0xffffffffu, v != 0);
    if (t == 0) g_is64 = (nz == 0u) ? 1 : 0;
}

// ---------------- preprocessing --------------------------------------------
__global__ void k_zero(int n) {
    int i = blockIdx.x * blockDim.x + threadIdx.x;
    if (i < n) g_deg[i] = 0;
}

__global__ void k_count(const int* __restrict__ w, int E, int n) {
    int e = blockIdx.x * blockDim.x + threadIdx.x;
    if (e >= E) return;
    int s, d;
    if (g_is64) { s = w[2 * e];  d = w[2 * E + 2 * e]; }
    else        { s = w[e];      d = w[E + e]; }
    s = min(max(s, 0), n - 1);
    d = min(max(d, 0), n - 1);
    g_src[e] = s;
    g_dst[e] = d;
    atomicAdd(&g_deg[d], 1);
}

__global__ void k_dis(int n) {
    int i = blockIdx.x * blockDim.x + threadIdx.x;
    if (i < n) g_dis[i] = rsqrtf((float)g_deg[i] + 1.0f);  // +1 self-loop
}

// exclusive scan of g_deg -> g_rowptr (3 phases)
__global__ void k_scan1(int n) {
    __shared__ int s[256];
    int t = threadIdx.x;
    int i = blockIdx.x * 256 + t;
    int v = (i < n) ? g_deg[i] : 0;
    s[t] = v;
    __syncthreads();
#pragma unroll
    for (int off = 1; off < 256; off <<= 1) {
        int u = (t >= off) ? s[t - off] : 0;
        __syncthreads();
        s[t] += u;
        __syncthreads();
    }
    if (i < n) g_rowptr[i] = s[t] - v;
    if (t == 255) g_blksum[blockIdx.x] = s[255];
}

__global__ void k_scan2(int nb) {
    __shared__ int s[512];
    int t = threadIdx.x;
    int v = (t < nb) ? g_blksum[t] : 0;
    s[t] = v;
    __syncthreads();
#pragma unroll
    for (int off = 1; off < 512; off <<= 1) {
        int u = (t >= off) ? s[t - off] : 0;
        __syncthreads();
        s[t] += u;
        __syncthreads();
    }
    if (t < nb) g_blksum[t] = s[t] - v;  // exclusive over blocks
}

__global__ void k_scan3(int n) {
    int i = blockIdx.x * blockDim.x + threadIdx.x;
    if (i < n) {
        int r = g_rowptr[i] + g_blksum[i >> 8];
        g_rowptr[i] = r;
        g_cursor[i] = r;
    }
}

__global__ void k_fill(int E) {
    int e = blockIdx.x * blockDim.x + threadIdx.x;
    if (e < E) {
        int s = g_src[e];
        int d = g_dst[e];
        int pos = atomicAdd(&g_cursor[d], 1);
        g_csr[pos] = make_int2(s, __float_as_int(g_dis[s] * g_dis[d]));
    }
}

// ---------------- register-tiled FP32 GEMM ----------------------------------
// COUT=128: X = Xext (harness x), H = g_h1.   COUT=64: X = g_a1 (+relu), H = g_h2.
template <int COUT, bool RELU_IN>
__global__ void k_gemm(const float* __restrict__ Xext, const float* __restrict__ W,
                       int nrows) {
    const float* X;
    float*       H;
    if constexpr (COUT == 128) { X = Xext;                 H = (float*)g_h1; }
    else                       { X = (const float*)g_a1;   H = (float*)g_h2; }

    constexpr int CG   = COUT / 8;
    constexpr int RG   = 256 / CG;
    constexpr int ROWS = RG * 4;
    constexpr int KC   = 32;

    __shared__ float xs[ROWS][KC + 4];
    __shared__ float ws[KC][COUT];

    const int tid  = threadIdx.x;
    const int txc  = tid % CG;
    const int tyr  = tid / CG;
    const int row0 = blockIdx.x * ROWS;

    float acc[4][8];
#pragma unroll
    for (int i = 0; i < 4; i++)
#pragma unroll
        for (int j = 0; j < 8; j++) acc[i][j] = 0.0f;

    for (int kc = 0; kc < 128; kc += KC) {
#pragma unroll
        for (int it = 0; it < (KC * COUT) / (256 * 4); it++) {
            int i4 = tid + it * 256;
            ((float4*)&ws[0][0])[i4] =
                *(const float4*)&W[(size_t)kc * COUT + (size_t)i4 * 4];
        }
#pragma unroll
        for (int it = 0; it < (ROWS * KC) / (256 * 4); it++) {
            int i4 = tid + it * 256;
            int r  = i4 / (KC / 4);
            int k4 = i4 % (KC / 4);
            int rg = row0 + r;
            float4 v = make_float4(0.f, 0.f, 0.f, 0.f);
            if (rg < nrows)
                v = *(const float4*)&X[(size_t)rg * 128 + kc + k4 * 4];
            if (RELU_IN) {
                v.x = fmaxf(v.x, 0.f); v.y = fmaxf(v.y, 0.f);
                v.z = fmaxf(v.z, 0.f); v.w = fmaxf(v.w, 0.f);
            }
            *(float4*)&xs[r][k4 * 4] = v;
        }
        __syncthreads();

#pragma unroll
        for (int kk = 0; kk < KC; kk++) {
            float a0 = xs[tyr * 4 + 0][kk];
            float a1 = xs[tyr * 4 + 1][kk];
            float a2 = xs[tyr * 4 + 2][kk];
            float a3 = xs[tyr * 4 + 3][kk];
            float4 b0 = *(const float4*)&ws[kk][txc * 8];
            float4 b1 = *(const float4*)&ws[kk][txc * 8 + 4];
            float bb[8] = {b0.x, b0.y, b0.z, b0.w, b1.x, b1.y, b1.z, b1.w};
#pragma unroll
            for (int j = 0; j < 8; j++) {
                acc[0][j] = fmaf(a0, bb[j], acc[0][j]);
                acc[1][j] = fmaf(a1, bb[j], acc[1][j]);
                acc[2][j] = fmaf(a2, bb[j], acc[2][j]);
                acc[3][j] = fmaf(a3, bb[j], acc[3][j]);
            }
        }
        __syncthreads();
    }

#pragma unroll
    for (int i = 0; i < 4; i++) {
        int r = row0 + tyr * 4 + i;
        if (r < nrows) {
            float4 s0 = make_float4(acc[i][0], acc[i][1], acc[i][2], acc[i][3]);
            float4 s1 = make_float4(acc[i][4], acc[i][5], acc[i][6], acc[i][7]);
            float4* hp = (float4*)&H[(size_t)r * COUT + txc * 8];
            hp[0] = s0;
            hp[1] = s1;
        }
    }
}

// ---------------- warp-per-node batched gather, layer 1 (128 cols) ----------
// lane q owns float4 q of the row. 32 edges loaded per batch (one per lane),
// broadcast via shfl; row-gather loads are independent -> deep MLP.
__global__ void k_gather1(const float* __restrict__ bias, int n) {
    int gw   = (blockIdx.x * blockDim.x + threadIdx.x) >> 5;
    int lane = threadIdx.x & 31;
    if (gw >= n) return;
    int i = gw;

    int   beg = g_rowptr[i];
    int   cnt = g_deg[i];
    float d   = g_dis[i];
    float d2  = d * d;

    float4 hv = g_h1[(size_t)i * 32 + lane];
    float4 bv = ((const float4*)bias)[lane];
    float4 acc;
    acc.x = fmaf(hv.x, d2, bv.x);
    acc.y = fmaf(hv.y, d2, bv.y);
    acc.z = fmaf(hv.z, d2, bv.z);
    acc.w = fmaf(hv.w, d2, bv.w);

    for (int e = 0; e < cnt; e += 32) {
        int  m  = min(cnt - e, 32);
        int2 ed = make_int2(0, 0);
        if (lane < m) ed = g_csr[beg + e + lane];
#pragma unroll 8
        for (int j = 0; j < m; j++) {
            int   s = __shfl_sync(0xffffffffu, ed.x, j);
            float w = __int_as_float(__shfl_sync(0xffffffffu, ed.y, j));
            float4 v = g_h1[(size_t)s * 32 + lane];
            acc.x = fmaf(v.x, w, acc.x);
            acc.y = fmaf(v.y, w, acc.y);
            acc.z = fmaf(v.z, w, acc.z);
            acc.w = fmaf(v.w, w, acc.w);
        }
    }
    g_a1[(size_t)i * 32 + lane] = acc;
}

// ---------------- warp-per-node batched gather, layer 2 (64 cols) -----------
// lane q owns float2 q of the row (32 lanes x float2 = 64 floats).
__global__ void k_gather2(const float* __restrict__ bias, float2* __restrict__ out,
                          int n) {
    int gw   = (blockIdx.x * blockDim.x + threadIdx.x) >> 5;
    int lane = threadIdx.x & 31;
    if (gw >= n) return;
    int i = gw;

    const float2* h2 = (const float2*)g_h2;

    int   beg = g_rowptr[i];
    int   cnt = g_deg[i];
    float d   = g_dis[i];
    float d2  = d * d;

    float2 hv = h2[(size_t)i * 32 + lane];
    float2 bv = ((const float2*)bias)[lane];
    float2 acc;
    acc.x = fmaf(hv.x, d2, bv.x);
    acc.y = fmaf(hv.y, d2, bv.y);

    for (int e = 0; e < cnt; e += 32) {
        int  m  = min(cnt - e, 32);
        int2 ed = make_int2(0, 0);
        if (lane < m) ed = g_csr[beg + e + lane];
#pragma unroll 8
        for (int j = 0; j < m; j++) {
            int   s = __shfl_sync(0xffffffffu, ed.x, j);
            float w = __int_as_float(__shfl_sync(0xffffffffu, ed.y, j));
            float2 v = h2[(size_t)s * 32 + lane];
            acc.x = fmaf(v.x, w, acc.x);
            acc.y = fmaf(v.y, w, acc.y);
        }
    }
    out[(size_t)i * 32 + lane] = acc;
}

// ---------------- launch -----------------------------------------------------
extern "C" void kernel_launch(void* const* d_in, const int* in_sizes, int n_in,
                              void* d_out, int out_size) {
    const float* x  = (const float*)d_in[0];
    const int*   ew = (const int*)d_in[1];    // int32 view of edge buffer
    const float* W1 = (const float*)d_in[2];
    const float* b1 = (const float*)d_in[3];
    const float* W2 = (const float*)d_in[4];
    const float* b2 = (const float*)d_in[5];

    const int N  = in_sizes[0] / 128;
    const int E  = in_sizes[1] / 2;
    const int nb = (N + 255) / 256;
    const int T  = 256;
    const int gblk = (N * 32 + T - 1) / T;    // warp per node, 8 warps/block

    // ---- edge dtype detect + normalization + dst-grouped CSR ----
    k_detect<<<1, 32>>>(ew);
    k_zero  <<<nb, T>>>(N);
    k_count <<<(E + T - 1) / T, T>>>(ew, E, N);
    k_dis   <<<nb, T>>>(N);
    k_scan1 <<<nb, T>>>(N);
    k_scan2 <<<1, 512>>>(nb);
    k_scan3 <<<nb, T>>>(N);
    k_fill  <<<(E + T - 1) / T, T>>>(E);

    // ---- layer 1: h1 = x @ W1 ; a1 = b1 + dis^2*h1 + gathered sum ----
    k_gemm<128, false><<<(N + 63) / 64, T>>>(x, W1, N);
    k_gather1<<<gblk, T>>>(b1, N);

    // ---- layer 2: h2 = relu(a1) @ W2 ; out = b2 + dis^2*h2 + sum ----
    k_gemm<64, true><<<(N + 127) / 128, T>>>(nullptr, W2, N);
    k_gather2<<<gblk, T>>>(b2, (float2*)d_out, N);
}